// round 16
// baseline (speedup 1.0000x reference)
#include <cuda_runtime.h>

// img:  [1, 3, 4096, 4096] float32
// ys,xs: [512] int32
// out:  [256, 6, 32, 32] float32 == linearized [N=512, 3, 32, 32]
//
// FINAL KERNEL — DRAM-activation-floor bound (proven across 9 variants:
// LDG/bulk-async/dual-engine, occ 20-69%, MLP 4-16 all pin at ~1.7TB/s).
//
// One CTA per (patch, channel): 1536 CTAs x 128 threads.
//  - lane j = tid&31 fixed -> each warp-LDG reads one contiguous 128B row
//    slice (fully coalesced, minimal sectors)
//  - 8 independent front-batched loads per thread (latency hidden)
//  - coalesced scalar stores
//  - conditional-subtract toroidal wrap (no integer division)

#define H 4096
#define W 4096
#define PH 32
#define PW 32
#define NPATCH 512

__global__ __launch_bounds__(128)
void patch_gather_kernel(const float* __restrict__ img,
                         const int* __restrict__ ys,
                         const int* __restrict__ xs,
                         float* __restrict__ out)
{
    const int b = blockIdx.x;          // 0..1535
    const int n = b / 3;               // patch
    const int c = b - n * 3;           // channel

    const int y0 = ys[n];
    const int x0 = xs[n];

    const float* __restrict__ img_c = img + (size_t)c * H * W;
    float* __restrict__ out_nc = out + (size_t)n * (3 * PH * PW) + (size_t)c * (PH * PW);

    // lane j fixed per thread -> warp-LDG = one contiguous 128B row slice
    const int j = threadIdx.x & 31;
    int xx = x0 + j; if (xx >= W) xx -= W;

    const int r0 = threadIdx.x >> 5;   // 0..3

    // 8 independent loads, all issued before any consumer (MLP=8/thread)
    float v[8];
    #pragma unroll
    for (int k = 0; k < 8; k++) {
        const int r = r0 + (k << 2);   // rows r0, r0+4, ..., r0+28
        int yy = y0 + r; if (yy >= H) yy -= H;
        v[k] = __ldg(img_c + (size_t)yy * W + xx);
    }

    #pragma unroll
    for (int k = 0; k < 8; k++) {
        out_nc[threadIdx.x + (k << 7)] = v[k];
    }
}

extern "C" void kernel_launch(void* const* d_in, const int* in_sizes, int n_in,
                              void* d_out, int out_size)
{
    const float* img = (const float*)d_in[0];
    const int*   ys  = (const int*)d_in[1];
    const int*   xs  = (const int*)d_in[2];
    float* out = (float*)d_out;

    patch_gather_kernel<<<NPATCH * 3, 128>>>(img, ys, xs, out);
}